// round 8
// baseline (speedup 1.0000x reference)
#include <cuda_runtime.h>

// axon_layer: dual-exponential PSP scan.
//   m_t = m_{t-1}*dm + x_t ; s_t = s_{t-1}*ds + x_t ; psp_t = (m_t - s_t)*v0
//
// Single-buffer smem staging (22.5 KB -> 8 blocks/SM, whole 1024-block grid
// resident in ONE wave) + distance-3 prefetch.global.L2 stream so DRAM reads
// are paced by dependency-free prefetches instead of smem-capacity-limited
// cp.async lookahead. cp.async then mostly hits L2 (~250cyc).
//
// Inputs: [0] input_spikes f32 [B,F,T]  [1] decay_m f32 [F]
//         [2] decay_s f32 [F]           [3] v_0 f32 scalar
// Output: psps [B,F,T] then m_T [B,F] then s_T [B,F].

#define AX_THREADS 128
#define AX_ROWS    128
#define AX_T       400
#define AX_CH4     10            // float4 per chunk (40 floats = 160 B/row)
#define AX_STRIDE  11            // padded smem row stride (odd -> no LDS conflicts)
#define AX_NCHUNK  10
#define AX_RQ      (AX_T / 4)    // 100 float4 per row
#define AX_ROWB    (AX_T * 4)    // 1600 bytes per row
#define AX_PFD     3             // prefetch distance in chunks

__device__ __forceinline__ void ax_cp_async16(void* smem_dst, const void* gmem_src) {
    unsigned saddr = (unsigned)__cvta_generic_to_shared(smem_dst);
    asm volatile("cp.async.cg.shared.global [%0], [%1], 16;\n"
                 :: "r"(saddr), "l"(gmem_src));
}
__device__ __forceinline__ void ax_cp_commit() {
    asm volatile("cp.async.commit_group;\n");
}
template <int N>
__device__ __forceinline__ void ax_cp_wait() {
    asm volatile("cp.async.wait_group %0;\n" :: "n"(N));
}
__device__ __forceinline__ void ax_prefetch_l2(const void* p) {
    asm volatile("prefetch.global.L2 [%0];" :: "l"(p));
}

extern __shared__ float4 ax_smem[];   // AX_ROWS * AX_STRIDE float4 = 22528 B

__device__ __forceinline__ void ax_issue_chunk(const float4* __restrict__ gin,
                                               float4* __restrict__ buf,
                                               int ch, int tid)
{
#pragma unroll
    for (int i = 0; i < AX_CH4; ++i) {
        int idx = i * AX_THREADS + tid;          // 0..1279 linear over tile
        int r = idx / AX_CH4;
        int c = idx - r * AX_CH4;
        ax_cp_async16(&buf[r * AX_STRIDE + c],
                      &gin[(long long)r * AX_RQ + ch * AX_CH4 + c]);
    }
    ax_cp_commit();
}

// Prefetch this thread's row segment for chunk ch into L2 (2 lines cover the
// 160B segment at any 64B phase of the row start).
__device__ __forceinline__ void ax_pf_chunk(const char* rowb, int ch) {
    ax_prefetch_l2(rowb + ch * (AX_CH4 * 16));
    ax_prefetch_l2(rowb + ch * (AX_CH4 * 16) + 128);
}

__global__ void __launch_bounds__(AX_THREADS, 8)
axon_pf_kernel(const float* __restrict__ x,
               const float* __restrict__ decay_m,
               const float* __restrict__ decay_s,
               const float* __restrict__ v0p,
               float* __restrict__ out,
               int F, long long n_rows)
{
    const int tid = threadIdx.x;
    const long long row0 = (long long)blockIdx.x * AX_ROWS;
    const long long my_row = row0 + tid;

    const float dm = __ldg(&decay_m[(int)(my_row % F)]);
    const float ds = __ldg(&decay_s[(int)(my_row % F)]);
    const float v0 = __ldg(v0p);

    float m = 0.0f, s = 0.0f;

    const float4* __restrict__ gin  = (const float4*)x + row0 * AX_RQ;
    float4* __restrict__       gout = (float4*)out     + row0 * AX_RQ;
    const char* rowb = (const char*)gin + (long long)tid * AX_ROWB;

    float4* buf = ax_smem;

    // ---- prologue: prefetch chunks 0..PFD-1 into L2, stage chunk 0 ----
#pragma unroll
    for (int pc = 0; pc < AX_PFD; ++pc) ax_pf_chunk(rowb, pc);
    ax_issue_chunk(gin, buf, 0, tid);

    const int rbase = tid * AX_STRIDE;

    for (int ch = 0; ch < AX_NCHUNK; ++ch) {
        ax_cp_wait<0>();          // chunk ch resident in smem
        __syncthreads();

        // keep the L2 prefetch stream running (no smem dependence)
        if (ch + AX_PFD < AX_NCHUNK) ax_pf_chunk(rowb, ch + AX_PFD);

        // ---- sequential scan along T for this thread's row (in place) ----
#pragma unroll
        for (int t4 = 0; t4 < AX_CH4; ++t4) {
            float4 q = buf[rbase + t4];
            float4 o;
            m = fmaf(m, dm, q.x); s = fmaf(s, ds, q.x); o.x = (m - s) * v0;
            m = fmaf(m, dm, q.y); s = fmaf(s, ds, q.y); o.y = (m - s) * v0;
            m = fmaf(m, dm, q.z); s = fmaf(s, ds, q.z); o.z = (m - s) * v0;
            m = fmaf(m, dm, q.w); s = fmaf(s, ds, q.w); o.w = (m - s) * v0;
            buf[rbase + t4] = o;
        }
        __syncthreads();

        // ---- coalesced store of chunk ch ----
#pragma unroll
        for (int i = 0; i < AX_CH4; ++i) {
            int idx = i * AX_THREADS + tid;
            int r = idx / AX_CH4;
            int c = idx - r * AX_CH4;
            gout[(long long)r * AX_RQ + ch * AX_CH4 + c] = buf[r * AX_STRIDE + c];
        }
        __syncthreads();          // buffer fully read -> reusable

        // ---- stage next chunk (mostly L2 hits thanks to prefetch) ----
        if (ch + 1 < AX_NCHUNK)
            ax_issue_chunk(gin, buf, ch + 1, tid);
    }

    // ---- final states ----
    const long long psps = n_rows * AX_T;
    out[psps + my_row]          = m;
    out[psps + n_rows + my_row] = s;
}

extern "C" void kernel_launch(void* const* d_in, const int* in_sizes, int n_in,
                              void* d_out, int out_size)
{
    const float* x   = (const float*)d_in[0];
    const float* dmv = (const float*)d_in[1];
    const float* dsv = (const float*)d_in[2];
    const float* v0p = (const float*)d_in[3];
    float* out = (float*)d_out;

    const int F = in_sizes[1];                       // 4096
    const long long total = (long long)in_sizes[0];  // B*F*T
    const long long n_rows = total / AX_T;           // B*F = 131072
    const int grid = (int)(n_rows / AX_ROWS);        // 1024

    const int smem_bytes = AX_ROWS * AX_STRIDE * (int)sizeof(float4); // 22528

    axon_pf_kernel<<<grid, AX_THREADS, smem_bytes>>>(
        x, dmv, dsv, v0p, out, F, n_rows);
}

// round 9
// speedup vs baseline: 1.5731x; 1.5731x over previous
#include <cuda_runtime.h>

// axon_layer: dual-exponential PSP scan.
//   m_t = m_{t-1}*dm + x_t ; s_t = s_{t-1}*ds + x_t ; psp_t = (m_t - s_t)*v0
//
// 4-stage cp.async ring, chunk = 10 float4/row (160 B), 64-row / 64-thread
// blocks. Sustained 3 chunks (30 KB) in flight per block; 45 KB smem ->
// 5 blocks/SM -> capacity 740 blocks; grid 2048 -> 2.77 units/slot -> ~92%
// scheduling utilization. Streaming stores to reduce L2 churn.
//
// Inputs: [0] input_spikes f32 [B,F,T]  [1] decay_m f32 [F]
//         [2] decay_s f32 [F]           [3] v_0 f32 scalar
// Output: psps [B,F,T] then m_T [B,F] then s_T [B,F].

#define AX_THREADS 64
#define AX_ROWS    64
#define AX_T       400
#define AX_CH4     10            // float4 per chunk (40 floats = 160 B/row)
#define AX_STRIDE  11            // padded smem row stride (gcd-free -> no LDS conflicts)
#define AX_NCHUNK  10
#define AX_NSTAGE  4
#define AX_RQ      (AX_T / 4)    // 100 float4 per row
#define AX_STAGEQ  (AX_ROWS * AX_STRIDE)   // 704 quads per stage

__device__ __forceinline__ void ax_cp_async16(void* smem_dst, const void* gmem_src) {
    unsigned saddr = (unsigned)__cvta_generic_to_shared(smem_dst);
    asm volatile("cp.async.cg.shared.global [%0], [%1], 16;\n"
                 :: "r"(saddr), "l"(gmem_src));
}
__device__ __forceinline__ void ax_cp_commit() {
    asm volatile("cp.async.commit_group;\n");
}
template <int N>
__device__ __forceinline__ void ax_cp_wait() {
    asm volatile("cp.async.wait_group %0;\n" :: "n"(N));
}

extern __shared__ float4 ax_smem[];   // AX_NSTAGE * AX_STAGEQ float4 = 45056 B

// Stage one chunk (64 rows x 10 quads) into a ring stage; always commits a
// group (possibly empty via ch >= AX_NCHUNK guard at call site) so group
// counting stays uniform.
__device__ __forceinline__ void ax_issue_chunk(const float4* __restrict__ gin,
                                               float4* __restrict__ stg,
                                               int ch, int tid)
{
#pragma unroll
    for (int i = 0; i < AX_CH4; ++i) {
        int idx = i * AX_THREADS + tid;          // 0..639 linear over tile
        int r = idx / AX_CH4;
        int c = idx - r * AX_CH4;
        ax_cp_async16(&stg[r * AX_STRIDE + c],
                      &gin[(long long)r * AX_RQ + ch * AX_CH4 + c]);
    }
}

__global__ void __launch_bounds__(AX_THREADS)
axon_ring_kernel(const float* __restrict__ x,
                 const float* __restrict__ decay_m,
                 const float* __restrict__ decay_s,
                 const float* __restrict__ v0p,
                 float* __restrict__ out,
                 int F, long long n_rows)
{
    const int tid = threadIdx.x;
    const long long row0 = (long long)blockIdx.x * AX_ROWS;
    const long long my_row = row0 + tid;

    const float dm = __ldg(&decay_m[(int)(my_row % F)]);
    const float ds = __ldg(&decay_s[(int)(my_row % F)]);
    const float v0 = __ldg(v0p);

    float m = 0.0f, s = 0.0f;

    const float4* __restrict__ gin  = (const float4*)x + row0 * AX_RQ;
    float*       __restrict__  goutf = out + row0 * AX_T;

    // ---- prologue: fill all 4 ring stages (chunks 0..3 in flight) ----
#pragma unroll
    for (int p = 0; p < AX_NSTAGE; ++p) {
        ax_issue_chunk(gin, ax_smem + p * AX_STAGEQ, p, tid);
        ax_cp_commit();
    }

    const int rbase = tid * AX_STRIDE;

    for (int ch = 0; ch < AX_NCHUNK; ++ch) {
        float4* stg = ax_smem + (ch & (AX_NSTAGE - 1)) * AX_STAGEQ;

        ax_cp_wait<AX_NSTAGE - 1>();   // chunk ch resident (in-order groups)
        __syncthreads();

        // ---- sequential scan along T for this thread's row (in place) ----
#pragma unroll
        for (int t4 = 0; t4 < AX_CH4; ++t4) {
            float4 q = stg[rbase + t4];
            float4 o;
            m = fmaf(m, dm, q.x); s = fmaf(s, ds, q.x); o.x = (m - s) * v0;
            m = fmaf(m, dm, q.y); s = fmaf(s, ds, q.y); o.y = (m - s) * v0;
            m = fmaf(m, dm, q.z); s = fmaf(s, ds, q.z); o.z = (m - s) * v0;
            m = fmaf(m, dm, q.w); s = fmaf(s, ds, q.w); o.w = (m - s) * v0;
            stg[rbase + t4] = o;
        }
        __syncthreads();

        // ---- coalesced streaming store of chunk ch ----
#pragma unroll
        for (int i = 0; i < AX_CH4; ++i) {
            int idx = i * AX_THREADS + tid;
            int r = idx / AX_CH4;
            int c = idx - r * AX_CH4;
            float4 v = stg[r * AX_STRIDE + c];
            __stcs((float4*)(goutf + (long long)r * AX_T + (ch * AX_CH4 + c) * 4), v);
        }
        __syncthreads();               // stage fully read -> reusable

        // ---- refill this stage with chunk ch+4 (empty group if past end) ----
        if (ch + AX_NSTAGE < AX_NCHUNK)
            ax_issue_chunk(gin, stg, ch + AX_NSTAGE, tid);
        ax_cp_commit();                // always commit: uniform group counting
    }

    // ---- final states ----
    const long long psps = n_rows * AX_T;
    out[psps + my_row]          = m;
    out[psps + n_rows + my_row] = s;
}

extern "C" void kernel_launch(void* const* d_in, const int* in_sizes, int n_in,
                              void* d_out, int out_size)
{
    const float* x   = (const float*)d_in[0];
    const float* dmv = (const float*)d_in[1];
    const float* dsv = (const float*)d_in[2];
    const float* v0p = (const float*)d_in[3];
    float* out = (float*)d_out;

    const int F = in_sizes[1];                       // 4096
    const long long total = (long long)in_sizes[0];  // B*F*T
    const long long n_rows = total / AX_T;           // B*F = 131072
    const int grid = (int)(n_rows / AX_ROWS);        // 2048

    const int smem_bytes = AX_NSTAGE * AX_STAGEQ * (int)sizeof(float4); // 45056

    static bool attr_set = false;
    if (!attr_set) {
        cudaFuncSetAttribute(axon_ring_kernel,
                             cudaFuncAttributeMaxDynamicSharedMemorySize,
                             smem_bytes);
        attr_set = true;
    }

    axon_ring_kernel<<<grid, AX_THREADS, smem_bytes>>>(
        x, dmv, dsv, v0p, out, F, n_rows);
}